// round 7
// baseline (speedup 1.0000x reference)
#include <cuda_runtime.h>

#define MAXN 50000
#define MAXE 1600000
#define RR 8

// Scratch: static device globals, referenced ONLY from device code.
__device__ __align__(16) float g_xw[(size_t)RR * MAXN * 64]; // [R][N][64] transformed feats
__device__ __align__(16) float g_h [(size_t)MAXN * 64];      // layer-1 output (pre-relu)
__device__ int g_cnt[MAXN * RR];       // (dst, relation) edge counts
__device__ int g_deg[MAXN];            // total in-degree per dst
__device__ int g_rowstart[MAXN + 1];   // CSR row starts (by dst)
__device__ int g_fill[MAXN];           // fill cursors
__device__ int g_blocksum[512];        // scan partials
__device__ int g_eidx[MAXE];           // packed (src<<3)|rel, grouped by dst
__device__ int g_w64;                  // bit0: edge_type is int64, bit1: edge_index is int64

__device__ __forceinline__ int clampi(int v, int lo, int hi) {
    return min(max(v, lo), hi);
}

// Load edge e's (src, dst, rel) honoring detected index width, fully clamped.
__device__ __forceinline__ void load_edge(const void* ei, const void* et, int E,
                                          int N, int e, int& src, int& dst, int& r) {
    int w = g_w64;
    if (w & 2) {
        const long long* p = (const long long*)ei;
        src = (int)p[e];
        dst = (int)p[(size_t)E + e];
    } else {
        const int* p = (const int*)ei;
        src = p[e];
        dst = p[(size_t)E + e];
    }
    if (w & 1) r = (int)((const long long*)et)[e];
    else       r = ((const int*)et)[e];
    src = clampi(src, 0, N - 1);
    dst = clampi(dst, 0, N - 1);
    r &= 7;
}

// ---------------------------------------------------------------- dtype probe
__global__ void detect_kernel(const void* ei, const void* et, int E, int N) {
    __shared__ int bad_et, bad_ei;
    if (threadIdx.x == 0) { bad_et = 0; bad_ei = 0; }
    __syncthreads();
    int M = min(E, 1024);   // 8KB worth of int64 reads — in-bounds for either dtype
    const long long* et64 = (const long long*)et;
    const long long* ei64 = (const long long*)ei;
    for (int i = threadIdx.x; i < M; i += blockDim.x) {
        long long v = et64[i];
        if (v < 0 || v >= RR) bad_et = 1;
        long long s = ei64[i];   // src half of edge_index
        if (s < 0 || s >= N) bad_ei = 1;
    }
    __syncthreads();
    if (threadIdx.x == 0) g_w64 = (bad_et ? 0 : 1) | (bad_ei ? 0 : 2);
}

// ---------------------------------------------------------------- CSR build
__global__ void zero_kernel(int n_cnt, int n_fill) {
    int i = blockIdx.x * blockDim.x + threadIdx.x;
    if (i < n_cnt) g_cnt[i] = 0;
    if (i < n_fill) g_fill[i] = 0;
}

__global__ void count_kernel(const void* ei, const void* et, int E, int N) {
    int e = blockIdx.x * blockDim.x + threadIdx.x;
    if (e < E) {
        int src, dst, r;
        load_edge(ei, et, E, N, e, src, dst, r);
        atomicAdd(&g_cnt[dst * RR + r], 1);
    }
}

// Block-level exclusive scan of per-dst degree; emit block totals.
__global__ void scan1_kernel(int N) {
    __shared__ int s[512];
    int d = blockIdx.x * 512 + threadIdx.x;
    int deg = 0;
    if (d < N) {
        for (int r = 0; r < RR; r++) deg += g_cnt[d * RR + r];
    }
    s[threadIdx.x] = deg;
    __syncthreads();
    for (int off = 1; off < 512; off <<= 1) {
        int v = (threadIdx.x >= off) ? s[threadIdx.x - off] : 0;
        __syncthreads();
        s[threadIdx.x] += v;
        __syncthreads();
    }
    int incl = s[threadIdx.x];
    if (d < N) { g_rowstart[d] = incl - deg; g_deg[d] = deg; }
    if (threadIdx.x == 511) g_blocksum[blockIdx.x] = incl;
}

__global__ void scan2_kernel(int nb) {
    __shared__ int s[512];
    int v = (threadIdx.x < nb) ? g_blocksum[threadIdx.x] : 0;
    s[threadIdx.x] = v;
    __syncthreads();
    for (int off = 1; off < 512; off <<= 1) {
        int p = (threadIdx.x >= off) ? s[threadIdx.x - off] : 0;
        __syncthreads();
        s[threadIdx.x] += p;
        __syncthreads();
    }
    if (threadIdx.x < nb) g_blocksum[threadIdx.x] = s[threadIdx.x] - v; // exclusive
}

__global__ void scan3_kernel(int N, int E) {
    int d = blockIdx.x * 512 + threadIdx.x;
    if (d < N) g_rowstart[d] += g_blocksum[blockIdx.x];
    if (d == 0) g_rowstart[N] = E;
}

__global__ void fill_kernel(const void* ei, const void* et, int E, int N) {
    int e = blockIdx.x * blockDim.x + threadIdx.x;
    if (e < E) {
        int src, dst, r;
        load_edge(ei, et, E, N, e, src, dst, r);
        int pos = g_rowstart[dst] + atomicAdd(&g_fill[dst], 1);
        pos = clampi(pos, 0, E - 1);
        g_eidx[pos] = (src << 3) | r;
    }
}

// ---------------------------------------------------------------- GEMM
// g_xw[r] = X @ Wrel[r] (r=0..7), plus root: X @ Wroot + b into rootout.
// LAYER1: X = Xarg, rootout = g_h. LAYER2: X = relu(g_h), rootout = Oarg.
// Block: 128 threads -> 64 nodes x 64 cols; thread: 2 nodes x 16 cols, scalar FFMA.
template <int K, int LAYER>
__global__ void gemm_kernel(const float* __restrict__ Xarg,
                            const float* __restrict__ Wrel,
                            const float* __restrict__ Wroot,
                            const float* __restrict__ bias,
                            float* __restrict__ Oarg, int N) {
    const float* X = (LAYER == 1) ? Xarg : g_h;
    float* rootout = (LAYER == 1) ? g_h : Oarg;

    __shared__ float xs[64][K + 1];
    int n0 = blockIdx.x * 64;

    const int NV = 64 * (K / 4);
    for (int idx = threadIdx.x; idx < NV; idx += blockDim.x) {
        int row = idx / (K / 4);
        int q   = idx % (K / 4);
        float4 v = make_float4(0.f, 0.f, 0.f, 0.f);
        if (n0 + row < N)
            v = reinterpret_cast<const float4*>(X)[(size_t)(n0 + row) * (K / 4) + q];
        if (LAYER == 2) {
            v.x = fmaxf(v.x, 0.f); v.y = fmaxf(v.y, 0.f);
            v.z = fmaxf(v.z, 0.f); v.w = fmaxf(v.w, 0.f);
        }
        xs[row][4 * q + 0] = v.x; xs[row][4 * q + 1] = v.y;
        xs[row][4 * q + 2] = v.z; xs[row][4 * q + 3] = v.w;
    }
    __syncthreads();

    int g = threadIdx.x & 3;    // column group: cols [g*16, g*16+16)
    int i = threadIdx.x >> 2;   // node sub-index 0..31; handles nodes i and i+32

    for (int r = 0; r < 9; r++) {
        const float* W = (r < 8) ? (Wrel + (size_t)r * K * 64) : Wroot;
        float acc0[16], acc1[16];
#pragma unroll
        for (int j = 0; j < 16; j++) { acc0[j] = 0.f; acc1[j] = 0.f; }

#pragma unroll 4
        for (int k = 0; k < K; k++) {
            const float4* lw =
                reinterpret_cast<const float4*>(W + (size_t)k * 64 + g * 16);
            float4 w0 = lw[0], w1 = lw[1], w2 = lw[2], w3 = lw[3];
            float wv[16] = {w0.x, w0.y, w0.z, w0.w, w1.x, w1.y, w1.z, w1.w,
                            w2.x, w2.y, w2.z, w2.w, w3.x, w3.y, w3.z, w3.w};
            float x0 = xs[i][k];
            float x1 = xs[i + 32][k];
#pragma unroll
            for (int j = 0; j < 16; j++) {
                acc0[j] = fmaf(wv[j], x0, acc0[j]);
                acc1[j] = fmaf(wv[j], x1, acc1[j]);
            }
        }

#pragma unroll
        for (int half = 0; half < 2; half++) {
            float* a = half ? acc1 : acc0;
            int node = n0 + i + half * 32;
            if (node < N) {
                if (r < 8) {
                    float4* o = reinterpret_cast<float4*>(
                        g_xw + ((size_t)r * N + node) * 64 + g * 16);
                    o[0] = make_float4(a[0],  a[1],  a[2],  a[3]);
                    o[1] = make_float4(a[4],  a[5],  a[6],  a[7]);
                    o[2] = make_float4(a[8],  a[9],  a[10], a[11]);
                    o[3] = make_float4(a[12], a[13], a[14], a[15]);
                } else {
                    const float4* bb = reinterpret_cast<const float4*>(bias) + g * 4;
                    float4 b0 = bb[0], b1 = bb[1], b2 = bb[2], b3 = bb[3];
                    float4* o = reinterpret_cast<float4*>(
                        rootout + (size_t)node * 64 + g * 16);
                    o[0] = make_float4(a[0] + b0.x,  a[1] + b0.y,
                                       a[2] + b0.z,  a[3] + b0.w);
                    o[1] = make_float4(a[4] + b1.x,  a[5] + b1.y,
                                       a[6] + b1.z,  a[7] + b1.w);
                    o[2] = make_float4(a[8] + b2.x,  a[9] + b2.y,
                                       a[10] + b2.z, a[11] + b2.w);
                    o[3] = make_float4(a[12] + b3.x, a[13] + b3.y,
                                       a[14] + b3.z, a[15] + b3.w);
                }
            }
        }
    }
}

// ---------------------------------------------------------------- Aggregation
// One 16-lane group per dst node; lane handles 4 contiguous cols (float4).
// Gathers g_xw[r][src], scales by 1/cnt(dst,r), accumulates in registers,
// adds into inout[dst] (which already holds root + bias). Atomic-free, shfl-free.
template <int LAYER>
__global__ void agg_kernel(float* __restrict__ Oarg, int N) {
    float* inout = (LAYER == 1) ? g_h : Oarg;

    int gidx = blockIdx.x * 16 + (threadIdx.x >> 4);
    int lane = threadIdx.x & 15;
    if (gidx >= N) return;

    int start = g_rowstart[gidx];
    int dg    = g_deg[gidx];

    // Every lane loads the full per-relation inverse-count row (L1 broadcast).
    float inv[RR];
#pragma unroll
    for (int r = 0; r < RR; r++) {
        int c = g_cnt[gidx * RR + r];
        inv[r] = 1.0f / (float)(c > 0 ? c : 1);
    }

    float4 acc = make_float4(0.f, 0.f, 0.f, 0.f);
    for (int i = 0; i < dg; i++) {
        int ep  = g_eidx[start + i];
        int r   = ep & 7;
        int src = ep >> 3;
        float sc = inv[r];
        float4 v = *reinterpret_cast<const float4*>(
            g_xw + ((size_t)r * N + src) * 64 + lane * 4);
        acc.x += v.x * sc; acc.y += v.y * sc;
        acc.z += v.z * sc; acc.w += v.w * sc;
    }

    float4* o = reinterpret_cast<float4*>(inout + (size_t)gidx * 64 + lane * 4);
    float4 old = *o;
    old.x += acc.x; old.y += acc.y; old.z += acc.z; old.w += acc.w;
    *o = old;
}

// ---------------------------------------------------------------- launch
extern "C" void kernel_launch(void* const* d_in, const int* in_sizes, int n_in,
                              void* d_out, int out_size) {
    const float* x   = (const float*)d_in[0];
    const void*  ei  = d_in[1];
    const void*  et  = d_in[2];
    const float* W1r = (const float*)d_in[3];
    const float* W1o = (const float*)d_in[4];
    const float* b1  = (const float*)d_in[5];
    const float* W2r = (const float*)d_in[6];
    const float* W2o = (const float*)d_in[7];
    const float* b2  = (const float*)d_in[8];
    float* out = (float*)d_out;

    int N = in_sizes[0] / 128;
    int E = in_sizes[2];

    // Detect index dtype (int32 vs int64), then CSR build (shared by both layers).
    detect_kernel<<<1, 256>>>(ei, et, E, N);
    zero_kernel<<<(N * RR + 255) / 256, 256>>>(N * RR, N);
    count_kernel<<<(E + 255) / 256, 256>>>(ei, et, E, N);
    int nb = (N + 511) / 512;
    scan1_kernel<<<nb, 512>>>(N);
    scan2_kernel<<<1, 512>>>(nb);
    scan3_kernel<<<nb, 512>>>(N, E);
    fill_kernel<<<(E + 255) / 256, 256>>>(ei, et, E, N);

    int gb = (N + 63) / 64;
    int ab = (N + 15) / 16;

    // Layer 1: scratch g_h holds root+bias, then aggregated messages.
    gemm_kernel<128, 1><<<gb, 128>>>(x, W1r, W1o, b1, nullptr, N);
    agg_kernel<1><<<ab, 256>>>(nullptr, N);

    // Layer 2: reads relu(g_h) internally, writes to harness out.
    gemm_kernel<64, 2><<<gb, 128>>>(nullptr, W2r, W2o, b2, out, N);
    agg_kernel<2><<<ab, 256>>>(out, N);
}

// round 8
// speedup vs baseline: 1.5785x; 1.5785x over previous
#include <cuda_runtime.h>

#define MAXN 50000
#define MAXE 1600000
#define RR 8

// Scratch: static device globals, referenced ONLY from device code.
__device__ __align__(16) float g_xw[(size_t)RR * MAXN * 64]; // [R][N][64] transformed feats
__device__ __align__(16) float g_h [(size_t)MAXN * 64];      // layer-1 output (pre-relu)
__device__ int g_cnt[MAXN * RR];       // (dst, relation) edge counts
__device__ int g_deg[MAXN];            // total in-degree per dst
__device__ int g_rowstart[MAXN];       // CSR row starts (block-local; add g_blocksum)
__device__ int g_fill[MAXN];           // fill cursors
__device__ int g_blocksum[512];        // scan partials (exclusive block offsets)
__device__ int g_eidx[MAXE];           // packed (src<<3)|rel, grouped by dst
__device__ int g_w64;                  // bit0: edge_type is int64, bit1: edge_index is int64

__device__ __forceinline__ int clampi(int v, int lo, int hi) {
    return min(max(v, lo), hi);
}

__device__ __forceinline__ void load_edge(const void* ei, const void* et, int E,
                                          int N, int e, int& src, int& dst, int& r) {
    int w = g_w64;
    if (w & 2) {
        const long long* p = (const long long*)ei;
        src = (int)p[e];
        dst = (int)p[(size_t)E + e];
    } else {
        const int* p = (const int*)ei;
        src = p[e];
        dst = p[(size_t)E + e];
    }
    if (w & 1) r = (int)((const long long*)et)[e];
    else       r = ((const int*)et)[e];
    src = clampi(src, 0, N - 1);
    dst = clampi(dst, 0, N - 1);
    r &= 7;
}

union A16 {
    unsigned long long u[8];
    float f[16];
};
__device__ __forceinline__ unsigned long long bcast2(float x) {
    unsigned long long r;
    asm("mov.b64 %0, {%1, %1};" : "=l"(r) : "r"(__float_as_uint(x)));
    return r;
}
__device__ __forceinline__ void fma2(unsigned long long& d, unsigned long long a,
                                     unsigned long long b) {
    asm("fma.rn.f32x2 %0, %1, %2, %0;" : "+l"(d) : "l"(a), "l"(b));
}

// ------------------------------------------------- dtype probe + zero (merged)
__global__ void dz_kernel(const void* ei, const void* et, int E, int N,
                          int n_cnt, int n_fill) {
    int i = blockIdx.x * blockDim.x + threadIdx.x;
    if (i < n_cnt) g_cnt[i] = 0;
    if (i < n_fill) g_fill[i] = 0;
    if (blockIdx.x == 0) {
        __shared__ int bad_et, bad_ei;
        if (threadIdx.x == 0) { bad_et = 0; bad_ei = 0; }
        __syncthreads();
        int M = min(E, 1024);
        const long long* et64 = (const long long*)et;
        const long long* ei64 = (const long long*)ei;
        for (int j = threadIdx.x; j < M; j += blockDim.x) {
            long long v = et64[j];
            if (v < 0 || v >= RR) bad_et = 1;
            long long s = ei64[j];
            if (s < 0 || s >= N) bad_ei = 1;
        }
        __syncthreads();
        if (threadIdx.x == 0) g_w64 = (bad_et ? 0 : 1) | (bad_ei ? 0 : 2);
    }
}

// ---------------------------------------------------------------- CSR build
__global__ void count_kernel(const void* ei, const void* et, int E, int N) {
    int e = blockIdx.x * blockDim.x + threadIdx.x;
    if (e < E) {
        int src, dst, r;
        load_edge(ei, et, E, N, e, src, dst, r);
        atomicAdd(&g_cnt[dst * RR + r], 1);
    }
}

__global__ void scan1_kernel(int N) {
    __shared__ int s[512];
    int d = blockIdx.x * 512 + threadIdx.x;
    int deg = 0;
    if (d < N) {
        for (int r = 0; r < RR; r++) deg += g_cnt[d * RR + r];
    }
    s[threadIdx.x] = deg;
    __syncthreads();
    for (int off = 1; off < 512; off <<= 1) {
        int v = (threadIdx.x >= off) ? s[threadIdx.x - off] : 0;
        __syncthreads();
        s[threadIdx.x] += v;
        __syncthreads();
    }
    int incl = s[threadIdx.x];
    if (d < N) { g_rowstart[d] = incl - deg; g_deg[d] = deg; }
    if (threadIdx.x == 511) g_blocksum[blockIdx.x] = incl;
}

__global__ void scan2_kernel(int nb) {
    __shared__ int s[512];
    int v = (threadIdx.x < nb) ? g_blocksum[threadIdx.x] : 0;
    s[threadIdx.x] = v;
    __syncthreads();
    for (int off = 1; off < 512; off <<= 1) {
        int p = (threadIdx.x >= off) ? s[threadIdx.x - off] : 0;
        __syncthreads();
        s[threadIdx.x] += p;
        __syncthreads();
    }
    if (threadIdx.x < nb) g_blocksum[threadIdx.x] = s[threadIdx.x] - v; // exclusive
}

__global__ void fill_kernel(const void* ei, const void* et, int E, int N) {
    int e = blockIdx.x * blockDim.x + threadIdx.x;
    if (e < E) {
        int src, dst, r;
        load_edge(ei, et, E, N, e, src, dst, r);
        int base = g_rowstart[dst] + g_blocksum[dst >> 9];
        int pos  = base + atomicAdd(&g_fill[dst], 1);
        pos = clampi(pos, 0, E - 1);
        g_eidx[pos] = (src << 3) | r;
    }
}

// ---------------------------------------------------------------- GEMM (f32x2)
// g_xw[r] = X @ Wrel[r] (r=0..7), plus root: X @ Wroot + b into rootout.
// LAYER1: X = Xarg, rootout = g_h. LAYER2: X = relu(g_h), rootout = Oarg.
// 128 threads -> 64 nodes x 64 cols; thread: 2 nodes x 16 cols, packed FFMA2.
template <int K, int LAYER>
__global__ void gemm_kernel(const float* __restrict__ Xarg,
                            const float* __restrict__ Wrel,
                            const float* __restrict__ Wroot,
                            const float* __restrict__ bias,
                            float* __restrict__ Oarg, int N) {
    const float* X = (LAYER == 1) ? Xarg : g_h;
    float* rootout = (LAYER == 1) ? g_h : Oarg;

    __shared__ float xs[64][K + 1];
    int n0 = blockIdx.x * 64;

    const int NV = 64 * (K / 4);
    for (int idx = threadIdx.x; idx < NV; idx += blockDim.x) {
        int row = idx / (K / 4);
        int q   = idx % (K / 4);
        float4 v = make_float4(0.f, 0.f, 0.f, 0.f);
        if (n0 + row < N)
            v = reinterpret_cast<const float4*>(X)[(size_t)(n0 + row) * (K / 4) + q];
        if (LAYER == 2) {
            v.x = fmaxf(v.x, 0.f); v.y = fmaxf(v.y, 0.f);
            v.z = fmaxf(v.z, 0.f); v.w = fmaxf(v.w, 0.f);
        }
        xs[row][4 * q + 0] = v.x; xs[row][4 * q + 1] = v.y;
        xs[row][4 * q + 2] = v.z; xs[row][4 * q + 3] = v.w;
    }
    __syncthreads();

    int g = threadIdx.x & 3;    // column group: cols [g*16, g*16+16)
    int i = threadIdx.x >> 2;   // node sub-index; handles nodes i and i+32

    for (int r = 0; r < 9; r++) {
        const float* W = (r < 8) ? (Wrel + (size_t)r * K * 64) : Wroot;
        A16 acc0, acc1;
#pragma unroll
        for (int j = 0; j < 8; j++) { acc0.u[j] = 0ull; acc1.u[j] = 0ull; }

#pragma unroll 4
        for (int k = 0; k < K; k++) {
            const ulonglong2* lw =
                reinterpret_cast<const ulonglong2*>(W + (size_t)k * 64 + g * 16);
            ulonglong2 l0 = lw[0], l1 = lw[1], l2 = lw[2], l3 = lw[3];
            unsigned long long w[8] = {l0.x, l0.y, l1.x, l1.y, l2.x, l2.y, l3.x, l3.y};
            unsigned long long x0 = bcast2(xs[i][k]);
            unsigned long long x1 = bcast2(xs[i + 32][k]);
#pragma unroll
            for (int j = 0; j < 8; j++) {
                fma2(acc0.u[j], w[j], x0);
                fma2(acc1.u[j], w[j], x1);
            }
        }

#pragma unroll
        for (int half = 0; half < 2; half++) {
            A16& a = half ? acc1 : acc0;
            int node = n0 + i + half * 32;
            if (node < N) {
                if (r < 8) {
                    float4* o = reinterpret_cast<float4*>(
                        g_xw + ((size_t)r * N + node) * 64 + g * 16);
                    o[0] = make_float4(a.f[0],  a.f[1],  a.f[2],  a.f[3]);
                    o[1] = make_float4(a.f[4],  a.f[5],  a.f[6],  a.f[7]);
                    o[2] = make_float4(a.f[8],  a.f[9],  a.f[10], a.f[11]);
                    o[3] = make_float4(a.f[12], a.f[13], a.f[14], a.f[15]);
                } else {
                    const float4* bb = reinterpret_cast<const float4*>(bias) + g * 4;
                    float4 b0 = bb[0], b1 = bb[1], b2 = bb[2], b3 = bb[3];
                    float4* o = reinterpret_cast<float4*>(
                        rootout + (size_t)node * 64 + g * 16);
                    o[0] = make_float4(a.f[0] + b0.x,  a.f[1] + b0.y,
                                       a.f[2] + b0.z,  a.f[3] + b0.w);
                    o[1] = make_float4(a.f[4] + b1.x,  a.f[5] + b1.y,
                                       a.f[6] + b1.z,  a.f[7] + b1.w);
                    o[2] = make_float4(a.f[8] + b2.x,  a.f[9] + b2.y,
                                       a.f[10] + b2.z, a.f[11] + b2.w);
                    o[3] = make_float4(a.f[12] + b3.x, a.f[13] + b3.y,
                                       a.f[14] + b3.z, a.f[15] + b3.w);
                }
            }
        }
    }
}

// ---------------------------------------------------------------- Aggregation
// One 16-lane group per dst node; lane handles 4 contiguous cols (float4).
// Unrolled x4: four independent gathers in flight per group (MLP ~4),
// two accumulator chains. Atomic-free.
template <int LAYER>
__global__ void agg_kernel(float* __restrict__ Oarg, int N) {
    float* inout = (LAYER == 1) ? g_h : Oarg;

    int gidx = blockIdx.x * 16 + (threadIdx.x >> 4);
    int lane = threadIdx.x & 15;
    if (gidx >= N) return;

    int start = g_rowstart[gidx] + g_blocksum[gidx >> 9];
    int dg    = g_deg[gidx];

    float inv[RR];
#pragma unroll
    for (int r = 0; r < RR; r++) {
        int c = g_cnt[gidx * RR + r];
        inv[r] = 1.0f / (float)(c > 0 ? c : 1);
    }

    const float* base = g_xw + (size_t)lane * 4;
    float4 accA = make_float4(0.f, 0.f, 0.f, 0.f);
    float4 accB = make_float4(0.f, 0.f, 0.f, 0.f);

    int i = 0;
    for (; i + 4 <= dg; i += 4) {
        int e0 = g_eidx[start + i];
        int e1 = g_eidx[start + i + 1];
        int e2 = g_eidx[start + i + 2];
        int e3 = g_eidx[start + i + 3];
        // addr = ((r*N + src) * 64); ep = (src<<3)|r  ->  r = ep&7, src = ep>>3
        float4 v0 = *reinterpret_cast<const float4*>(
            base + ((size_t)(e0 & 7) * N + (e0 >> 3)) * 64);
        float4 v1 = *reinterpret_cast<const float4*>(
            base + ((size_t)(e1 & 7) * N + (e1 >> 3)) * 64);
        float4 v2 = *reinterpret_cast<const float4*>(
            base + ((size_t)(e2 & 7) * N + (e2 >> 3)) * 64);
        float4 v3 = *reinterpret_cast<const float4*>(
            base + ((size_t)(e3 & 7) * N + (e3 >> 3)) * 64);
        float s0 = inv[e0 & 7], s1 = inv[e1 & 7], s2 = inv[e2 & 7], s3 = inv[e3 & 7];
        accA.x = fmaf(v0.x, s0, accA.x); accA.y = fmaf(v0.y, s0, accA.y);
        accA.z = fmaf(v0.z, s0, accA.z); accA.w = fmaf(v0.w, s0, accA.w);
        accB.x = fmaf(v1.x, s1, accB.x); accB.y = fmaf(v1.y, s1, accB.y);
        accB.z = fmaf(v1.z, s1, accB.z); accB.w = fmaf(v1.w, s1, accB.w);
        accA.x = fmaf(v2.x, s2, accA.x); accA.y = fmaf(v2.y, s2, accA.y);
        accA.z = fmaf(v2.z, s2, accA.z); accA.w = fmaf(v2.w, s2, accA.w);
        accB.x = fmaf(v3.x, s3, accB.x); accB.y = fmaf(v3.y, s3, accB.y);
        accB.z = fmaf(v3.z, s3, accB.z); accB.w = fmaf(v3.w, s3, accB.w);
    }
    for (; i < dg; i++) {
        int e0 = g_eidx[start + i];
        float s0 = inv[e0 & 7];
        float4 v0 = *reinterpret_cast<const float4*>(
            base + ((size_t)(e0 & 7) * N + (e0 >> 3)) * 64);
        accA.x = fmaf(v0.x, s0, accA.x); accA.y = fmaf(v0.y, s0, accA.y);
        accA.z = fmaf(v0.z, s0, accA.z); accA.w = fmaf(v0.w, s0, accA.w);
    }

    float4* o = reinterpret_cast<float4*>(inout + (size_t)gidx * 64 + lane * 4);
    float4 old = *o;
    old.x += accA.x + accB.x; old.y += accA.y + accB.y;
    old.z += accA.z + accB.z; old.w += accA.w + accB.w;
    *o = old;
}

// ---------------------------------------------------------------- launch
extern "C" void kernel_launch(void* const* d_in, const int* in_sizes, int n_in,
                              void* d_out, int out_size) {
    const float* x   = (const float*)d_in[0];
    const void*  ei  = d_in[1];
    const void*  et  = d_in[2];
    const float* W1r = (const float*)d_in[3];
    const float* W1o = (const float*)d_in[4];
    const float* b1  = (const float*)d_in[5];
    const float* W2r = (const float*)d_in[6];
    const float* W2o = (const float*)d_in[7];
    const float* b2  = (const float*)d_in[8];
    float* out = (float*)d_out;

    int N = in_sizes[0] / 128;
    int E = in_sizes[2];

    dz_kernel<<<(N * RR + 255) / 256, 256>>>(ei, et, E, N, N * RR, N);
    count_kernel<<<(E + 255) / 256, 256>>>(ei, et, E, N);
    int nb = (N + 511) / 512;
    scan1_kernel<<<nb, 512>>>(N);
    scan2_kernel<<<1, 512>>>(nb);
    fill_kernel<<<(E + 255) / 256, 256>>>(ei, et, E, N);

    int gb = (N + 63) / 64;
    int ab = (N + 15) / 16;

    gemm_kernel<128, 1><<<gb, 128>>>(x, W1r, W1o, b1, nullptr, N);
    agg_kernel<1><<<ab, 256>>>(nullptr, N);

    gemm_kernel<64, 2><<<gb, 128>>>(nullptr, W2r, W2o, b2, out, N);
    agg_kernel<2><<<ab, 256>>>(out, N);
}

// round 9
// speedup vs baseline: 1.7046x; 1.0799x over previous
#include <cuda_runtime.h>

#define MAXN 50000
#define MAXE 1600000
#define RR 8

// Scratch: static device globals, referenced ONLY from device code.
__device__ __align__(16) float g_xw[(size_t)RR * MAXN * 64]; // [R][N][64] transformed feats
__device__ __align__(16) float g_h [(size_t)MAXN * 64];      // layer-1 output (pre-relu)
__device__ int g_cnt[MAXN * RR];       // (dst, relation) edge counts
__device__ int g_deg[MAXN];            // total in-degree per dst
__device__ int g_rowstart[MAXN];       // CSR row starts (block-local; add g_blocksum)
__device__ int g_fill[MAXN];           // fill cursors
__device__ int g_blocksum[512];        // scan partials (exclusive block offsets)
__device__ int g_eidx[MAXE];           // packed (src<<3)|rel, grouped by dst
__device__ int g_w64;                  // bit0: edge_type is int64, bit1: edge_index is int64

__device__ __forceinline__ int clampi(int v, int lo, int hi) {
    return min(max(v, lo), hi);
}

__device__ __forceinline__ void load_edge(const void* ei, const void* et, int E,
                                          int N, int e, int& src, int& dst, int& r) {
    int w = g_w64;
    if (w & 2) {
        const long long* p = (const long long*)ei;
        src = (int)p[e];
        dst = (int)p[(size_t)E + e];
    } else {
        const int* p = (const int*)ei;
        src = p[e];
        dst = p[(size_t)E + e];
    }
    if (w & 1) r = (int)((const long long*)et)[e];
    else       r = ((const int*)et)[e];
    src = clampi(src, 0, N - 1);
    dst = clampi(dst, 0, N - 1);
    r &= 7;
}

__device__ __forceinline__ unsigned long long bcast2(float x) {
    unsigned long long r;
    asm("mov.b64 %0, {%1, %1};" : "=l"(r) : "r"(__float_as_uint(x)));
    return r;
}
__device__ __forceinline__ void fma2(unsigned long long& d, unsigned long long a,
                                     unsigned long long b) {
    asm("fma.rn.f32x2 %0, %1, %2, %0;" : "+l"(d) : "l"(a), "l"(b));
}
__device__ __forceinline__ float lo2(unsigned long long v) {
    return __uint_as_float((unsigned)(v & 0xffffffffull));
}
__device__ __forceinline__ float hi2(unsigned long long v) {
    return __uint_as_float((unsigned)(v >> 32));
}

// ------------------------------------------------- dtype probe + zero (merged)
__global__ void dz_kernel(const void* ei, const void* et, int E, int N,
                          int n_cnt, int n_fill) {
    int i = blockIdx.x * blockDim.x + threadIdx.x;
    if (i < n_cnt) g_cnt[i] = 0;
    if (i < n_fill) g_fill[i] = 0;
    if (blockIdx.x == 0) {
        __shared__ int bad_et, bad_ei;
        if (threadIdx.x == 0) { bad_et = 0; bad_ei = 0; }
        __syncthreads();
        int M = min(E, 1024);
        const long long* et64 = (const long long*)et;
        const long long* ei64 = (const long long*)ei;
        for (int j = threadIdx.x; j < M; j += blockDim.x) {
            long long v = et64[j];
            if (v < 0 || v >= RR) bad_et = 1;
            long long s = ei64[j];
            if (s < 0 || s >= N) bad_ei = 1;
        }
        __syncthreads();
        if (threadIdx.x == 0) g_w64 = (bad_et ? 0 : 1) | (bad_ei ? 0 : 2);
    }
}

// ---------------------------------------------------------------- CSR build
__global__ void count_kernel(const void* ei, const void* et, int E, int N) {
    int e = blockIdx.x * blockDim.x + threadIdx.x;
    if (e < E) {
        int src, dst, r;
        load_edge(ei, et, E, N, e, src, dst, r);
        atomicAdd(&g_cnt[dst * RR + r], 1);
    }
}

__global__ void scan1_kernel(int N) {
    __shared__ int s[512];
    int d = blockIdx.x * 512 + threadIdx.x;
    int deg = 0;
    if (d < N) {
        for (int r = 0; r < RR; r++) deg += g_cnt[d * RR + r];
    }
    s[threadIdx.x] = deg;
    __syncthreads();
    for (int off = 1; off < 512; off <<= 1) {
        int v = (threadIdx.x >= off) ? s[threadIdx.x - off] : 0;
        __syncthreads();
        s[threadIdx.x] += v;
        __syncthreads();
    }
    int incl = s[threadIdx.x];
    if (d < N) { g_rowstart[d] = incl - deg; g_deg[d] = deg; }
    if (threadIdx.x == 511) g_blocksum[blockIdx.x] = incl;
}

__global__ void scan2_kernel(int nb) {
    __shared__ int s[512];
    int v = (threadIdx.x < nb) ? g_blocksum[threadIdx.x] : 0;
    s[threadIdx.x] = v;
    __syncthreads();
    for (int off = 1; off < 512; off <<= 1) {
        int p = (threadIdx.x >= off) ? s[threadIdx.x - off] : 0;
        __syncthreads();
        s[threadIdx.x] += p;
        __syncthreads();
    }
    if (threadIdx.x < nb) g_blocksum[threadIdx.x] = s[threadIdx.x] - v; // exclusive
}

__global__ void fill_kernel(const void* ei, const void* et, int E, int N) {
    int e = blockIdx.x * blockDim.x + threadIdx.x;
    if (e < E) {
        int src, dst, r;
        load_edge(ei, et, E, N, e, src, dst, r);
        int base = g_rowstart[dst] + g_blocksum[dst >> 9];
        int pos  = base + atomicAdd(&g_fill[dst], 1);
        pos = clampi(pos, 0, E - 1);
        g_eidx[pos] = (src << 3) | r;
    }
}

// ---------------------------------------------------------------- GEMM (f32x2)
// g_xw[r] = X @ Wrel[r] (r=0..7), plus root: X @ Wroot + b into rootout.
// LAYER1: X = Xarg, rootout = g_h. LAYER2: X = relu(g_h), rootout = Oarg.
// 128 threads -> 64 nodes x 64 cols; thread: 4 nodes x 8 cols.
// Per k: 2 LDG.128 (W) + 4 LDS + 16 FMA2  => FMA2:LDG = 8:1 (FMA-pipe bound).
template <int K, int LAYER>
__global__ void gemm_kernel(const float* __restrict__ Xarg,
                            const float* __restrict__ Wrel,
                            const float* __restrict__ Wroot,
                            const float* __restrict__ bias,
                            float* __restrict__ Oarg, int N) {
    const float* X = (LAYER == 1) ? Xarg : g_h;
    float* rootout = (LAYER == 1) ? g_h : Oarg;

    __shared__ float xs[64][K + 1];
    int n0 = blockIdx.x * 64;

    const int NV = 64 * (K / 4);
    for (int idx = threadIdx.x; idx < NV; idx += blockDim.x) {
        int row = idx / (K / 4);
        int q   = idx % (K / 4);
        float4 v = make_float4(0.f, 0.f, 0.f, 0.f);
        if (n0 + row < N)
            v = reinterpret_cast<const float4*>(X)[(size_t)(n0 + row) * (K / 4) + q];
        if (LAYER == 2) {
            v.x = fmaxf(v.x, 0.f); v.y = fmaxf(v.y, 0.f);
            v.z = fmaxf(v.z, 0.f); v.w = fmaxf(v.w, 0.f);
        }
        xs[row][4 * q + 0] = v.x; xs[row][4 * q + 1] = v.y;
        xs[row][4 * q + 2] = v.z; xs[row][4 * q + 3] = v.w;
    }
    __syncthreads();

    int cg = threadIdx.x & 7;   // column group: cols [cg*8, cg*8+8)
    int i  = threadIdx.x >> 3;  // node sub-index 0..15; nodes i, i+16, i+32, i+48

    for (int r = 0; r < 9; r++) {
        const float* W = (r < 8) ? (Wrel + (size_t)r * K * 64) : Wroot;
        unsigned long long acc[4][4];
#pragma unroll
        for (int n = 0; n < 4; n++)
#pragma unroll
            for (int j = 0; j < 4; j++) acc[n][j] = 0ull;

#pragma unroll 4
        for (int k = 0; k < K; k++) {
            const ulonglong2* lw =
                reinterpret_cast<const ulonglong2*>(W + (size_t)k * 64 + cg * 8);
            ulonglong2 l0 = lw[0], l1 = lw[1];
            unsigned long long w[4] = {l0.x, l0.y, l1.x, l1.y};
            unsigned long long xv[4];
            xv[0] = bcast2(xs[i][k]);
            xv[1] = bcast2(xs[i + 16][k]);
            xv[2] = bcast2(xs[i + 32][k]);
            xv[3] = bcast2(xs[i + 48][k]);
#pragma unroll
            for (int n = 0; n < 4; n++)
#pragma unroll
                for (int j = 0; j < 4; j++)
                    fma2(acc[n][j], w[j], xv[n]);
        }

#pragma unroll
        for (int n = 0; n < 4; n++) {
            int node = n0 + i + n * 16;
            if (node < N) {
                if (r < 8) {
                    float4* o = reinterpret_cast<float4*>(
                        g_xw + ((size_t)r * N + node) * 64 + cg * 8);
                    o[0] = make_float4(lo2(acc[n][0]), hi2(acc[n][0]),
                                       lo2(acc[n][1]), hi2(acc[n][1]));
                    o[1] = make_float4(lo2(acc[n][2]), hi2(acc[n][2]),
                                       lo2(acc[n][3]), hi2(acc[n][3]));
                } else {
                    const float4* bb = reinterpret_cast<const float4*>(bias) + cg * 2;
                    float4 b0 = bb[0], b1 = bb[1];
                    float4* o = reinterpret_cast<float4*>(
                        rootout + (size_t)node * 64 + cg * 8);
                    o[0] = make_float4(lo2(acc[n][0]) + b0.x, hi2(acc[n][0]) + b0.y,
                                       lo2(acc[n][1]) + b0.z, hi2(acc[n][1]) + b0.w);
                    o[1] = make_float4(lo2(acc[n][2]) + b1.x, hi2(acc[n][2]) + b1.y,
                                       lo2(acc[n][3]) + b1.z, hi2(acc[n][3]) + b1.w);
                }
            }
        }
    }
}

// ---------------------------------------------------------------- Aggregation
// One WARP per dst node (no intra-warp divergence); lane handles 2 cols (float2).
// Unrolled x4: four independent 256B gathers in flight; two accumulator chains.
template <int LAYER>
__global__ void agg_kernel(float* __restrict__ Oarg, int N) {
    float* inout = (LAYER == 1) ? g_h : Oarg;

    int dst  = blockIdx.x * 8 + (threadIdx.x >> 5);
    int lane = threadIdx.x & 31;
    if (dst >= N) return;

    int start = g_rowstart[dst] + g_blocksum[dst >> 9];
    int dg    = g_deg[dst];

    float inv[RR];
#pragma unroll
    for (int r = 0; r < RR; r++) {
        int c = g_cnt[dst * RR + r];
        inv[r] = 1.0f / (float)(c > 0 ? c : 1);
    }

    const float* base = g_xw + (size_t)lane * 2;
    float2 accA = make_float2(0.f, 0.f);
    float2 accB = make_float2(0.f, 0.f);

    int i = 0;
    for (; i + 4 <= dg; i += 4) {
        int e0 = g_eidx[start + i];
        int e1 = g_eidx[start + i + 1];
        int e2 = g_eidx[start + i + 2];
        int e3 = g_eidx[start + i + 3];
        float2 v0 = *reinterpret_cast<const float2*>(
            base + ((size_t)(e0 & 7) * N + (e0 >> 3)) * 64);
        float2 v1 = *reinterpret_cast<const float2*>(
            base + ((size_t)(e1 & 7) * N + (e1 >> 3)) * 64);
        float2 v2 = *reinterpret_cast<const float2*>(
            base + ((size_t)(e2 & 7) * N + (e2 >> 3)) * 64);
        float2 v3 = *reinterpret_cast<const float2*>(
            base + ((size_t)(e3 & 7) * N + (e3 >> 3)) * 64);
        float s0 = inv[e0 & 7], s1 = inv[e1 & 7], s2 = inv[e2 & 7], s3 = inv[e3 & 7];
        accA.x = fmaf(v0.x, s0, accA.x); accA.y = fmaf(v0.y, s0, accA.y);
        accB.x = fmaf(v1.x, s1, accB.x); accB.y = fmaf(v1.y, s1, accB.y);
        accA.x = fmaf(v2.x, s2, accA.x); accA.y = fmaf(v2.y, s2, accA.y);
        accB.x = fmaf(v3.x, s3, accB.x); accB.y = fmaf(v3.y, s3, accB.y);
    }
    for (; i < dg; i++) {
        int e0 = g_eidx[start + i];
        float s0 = inv[e0 & 7];
        float2 v0 = *reinterpret_cast<const float2*>(
            base + ((size_t)(e0 & 7) * N + (e0 >> 3)) * 64);
        accA.x = fmaf(v0.x, s0, accA.x); accA.y = fmaf(v0.y, s0, accA.y);
    }

    float2* o = reinterpret_cast<float2*>(inout + (size_t)dst * 64 + lane * 2);
    float2 old = *o;
    old.x += accA.x + accB.x;
    old.y += accA.y + accB.y;
    *o = old;
}

// ---------------------------------------------------------------- launch
extern "C" void kernel_launch(void* const* d_in, const int* in_sizes, int n_in,
                              void* d_out, int out_size) {
    const float* x   = (const float*)d_in[0];
    const void*  ei  = d_in[1];
    const void*  et  = d_in[2];
    const float* W1r = (const float*)d_in[3];
    const float* W1o = (const float*)d_in[4];
    const float* b1  = (const float*)d_in[5];
    const float* W2r = (const float*)d_in[6];
    const float* W2o = (const float*)d_in[7];
    const float* b2  = (const float*)d_in[8];
    float* out = (float*)d_out;

    int N = in_sizes[0] / 128;
    int E = in_sizes[2];

    int nb = (N + 511) / 512;
    int gb = (N + 63) / 64;
    int ab = (N + 7) / 8;

    // Launch order chosen so the heavy gemm1 sits at launch index 3
    // (where the ncu capture window lands). Dependencies preserved on stream 0.
    dz_kernel<<<(N * RR + 255) / 256, 256>>>(ei, et, E, N, N * RR, N);      // 0
    count_kernel<<<(E + 255) / 256, 256>>>(ei, et, E, N);                    // 1
    scan1_kernel<<<nb, 512>>>(N);                                            // 2
    gemm_kernel<128, 1><<<gb, 128>>>(x, W1r, W1o, b1, nullptr, N);           // 3
    scan2_kernel<<<1, 512>>>(nb);                                            // 4
    fill_kernel<<<(E + 255) / 256, 256>>>(ei, et, E, N);                     // 5
    agg_kernel<1><<<ab, 256>>>(nullptr, N);                                  // 6
    gemm_kernel<64, 2><<<gb, 128>>>(nullptr, W2r, W2o, b2, out, N);          // 7
    agg_kernel<2><<<ab, 256>>>(out, N);                                      // 8
}

// round 10
// speedup vs baseline: 2.4732x; 1.4509x over previous
#include <cuda_runtime.h>

#define MAXN 50000
#define MAXE 1600000
#define RR 8

// Scratch: static device globals, referenced ONLY from device code.
__device__ __align__(16) float g_xw[(size_t)RR * MAXN * 64]; // [R][N][64] transformed feats
__device__ __align__(16) float g_h [(size_t)MAXN * 64];      // layer-1 output (pre-relu)
__device__ int g_cnt[MAXN * RR];       // (dst, relation) edge counts
__device__ int g_deg[MAXN];            // total in-degree per dst
__device__ int g_rowstart[MAXN];       // CSR row starts (block-local; add g_blocksum)
__device__ int g_fill[MAXN];           // fill cursors
__device__ int g_blocksum[512];        // scan partials (exclusive block offsets)
__device__ int g_eidx[MAXE];           // packed (src<<3)|rel, grouped by dst
__device__ int g_w64;                  // bit0: edge_type is int64, bit1: edge_index is int64

__device__ __forceinline__ int clampi(int v, int lo, int hi) {
    return min(max(v, lo), hi);
}

__device__ __forceinline__ void load_edge(const void* ei, const void* et, int E,
                                          int N, int e, int& src, int& dst, int& r) {
    int w = g_w64;
    if (w & 2) {
        const long long* p = (const long long*)ei;
        src = (int)p[e];
        dst = (int)p[(size_t)E + e];
    } else {
        const int* p = (const int*)ei;
        src = p[e];
        dst = p[(size_t)E + e];
    }
    if (w & 1) r = (int)((const long long*)et)[e];
    else       r = ((const int*)et)[e];
    src = clampi(src, 0, N - 1);
    dst = clampi(dst, 0, N - 1);
    r &= 7;
}

__device__ __forceinline__ unsigned long long bcast2(float x) {
    unsigned long long r;
    asm("mov.b64 %0, {%1, %1};" : "=l"(r) : "r"(__float_as_uint(x)));
    return r;
}
__device__ __forceinline__ void fma2(unsigned long long& d, unsigned long long a,
                                     unsigned long long b) {
    asm("fma.rn.f32x2 %0, %1, %2, %0;" : "+l"(d) : "l"(a), "l"(b));
}
__device__ __forceinline__ float lo2(unsigned long long v) {
    return __uint_as_float((unsigned)(v & 0xffffffffull));
}
__device__ __forceinline__ float hi2(unsigned long long v) {
    return __uint_as_float((unsigned)(v >> 32));
}

// ------------------------------------------------- dtype probe + zero (merged)
__global__ void dz_kernel(const void* ei, const void* et, int E, int N,
                          int n_cnt, int n_fill) {
    int i = blockIdx.x * blockDim.x + threadIdx.x;
    if (i < n_cnt) g_cnt[i] = 0;
    if (i < n_fill) g_fill[i] = 0;
    if (blockIdx.x == 0) {
        __shared__ int bad_et, bad_ei;
        if (threadIdx.x == 0) { bad_et = 0; bad_ei = 0; }
        __syncthreads();
        int M = min(E, 1024);
        const long long* et64 = (const long long*)et;
        const long long* ei64 = (const long long*)ei;
        for (int j = threadIdx.x; j < M; j += blockDim.x) {
            long long v = et64[j];
            if (v < 0 || v >= RR) bad_et = 1;
            long long s = ei64[j];
            if (s < 0 || s >= N) bad_ei = 1;
        }
        __syncthreads();
        if (threadIdx.x == 0) g_w64 = (bad_et ? 0 : 1) | (bad_ei ? 0 : 2);
    }
}

// ---------------------------------------------------------------- CSR build
__global__ void count_kernel(const void* ei, const void* et, int E, int N) {
    int e = blockIdx.x * blockDim.x + threadIdx.x;
    if (e < E) {
        int src, dst, r;
        load_edge(ei, et, E, N, e, src, dst, r);
        atomicAdd(&g_cnt[dst * RR + r], 1);
    }
}

__global__ void scan1_kernel(int N) {
    __shared__ int s[512];
    int d = blockIdx.x * 512 + threadIdx.x;
    int deg = 0;
    if (d < N) {
        for (int r = 0; r < RR; r++) deg += g_cnt[d * RR + r];
    }
    s[threadIdx.x] = deg;
    __syncthreads();
    for (int off = 1; off < 512; off <<= 1) {
        int v = (threadIdx.x >= off) ? s[threadIdx.x - off] : 0;
        __syncthreads();
        s[threadIdx.x] += v;
        __syncthreads();
    }
    int incl = s[threadIdx.x];
    if (d < N) { g_rowstart[d] = incl - deg; g_deg[d] = deg; }
    if (threadIdx.x == 511) g_blocksum[blockIdx.x] = incl;
}

__global__ void scan2_kernel(int nb) {
    __shared__ int s[512];
    int v = (threadIdx.x < nb) ? g_blocksum[threadIdx.x] : 0;
    s[threadIdx.x] = v;
    __syncthreads();
    for (int off = 1; off < 512; off <<= 1) {
        int p = (threadIdx.x >= off) ? s[threadIdx.x - off] : 0;
        __syncthreads();
        s[threadIdx.x] += p;
        __syncthreads();
    }
    if (threadIdx.x < nb) g_blocksum[threadIdx.x] = s[threadIdx.x] - v; // exclusive
}

__global__ void fill_kernel(const void* ei, const void* et, int E, int N) {
    int e = blockIdx.x * blockDim.x + threadIdx.x;
    if (e < E) {
        int src, dst, r;
        load_edge(ei, et, E, N, e, src, dst, r);
        int base = g_rowstart[dst] + g_blocksum[dst >> 9];
        int pos  = base + atomicAdd(&g_fill[dst], 1);
        pos = clampi(pos, 0, E - 1);
        g_eidx[pos] = (src << 3) | r;
    }
}

// ---------------------------------------------------------------- GEMM (f32x2)
// g_xw[r] = X @ Wrel[r] (r=0..7), plus root: X @ Wroot + b into rootout.
// LAYER1: X = Xarg, rootout = g_h. LAYER2: X = relu(g_h), rootout = Oarg.
// X tile stored TRANSPOSED in smem: xs[k][node] (72-float padded rows), so the
// 8 node-values a thread needs for a k-step load as 2x LDS.128 whose 64-bit
// halves are directly the packed f32x2 node-pairs (no movs, no scalar LDS).
// 128 threads -> 64 nodes x 64 cols; thread: 8 nodes x 4 cols.
// Per k: 1 LDG.128 (W) + 2 LDS.128 (x) + 4 bcast + 16 FFMA2.
template <int K, int LAYER>
__global__ void gemm_kernel(const float* __restrict__ Xarg,
                            const float* __restrict__ Wrel,
                            const float* __restrict__ Wroot,
                            const float* __restrict__ bias,
                            float* __restrict__ Oarg, int N) {
    const float* X = (LAYER == 1) ? Xarg : g_h;
    float* rootout = (LAYER == 1) ? g_h : Oarg;

    __shared__ float xs[K][72];   // [k][node], 72-float rows (16B-aligned, bank-safe)
    int n0 = blockIdx.x * 64;

    // Load + transpose the X tile. idx -> (row = idx&63, q = idx>>6) keeps the
    // transposed STS bank-conflict-free (consecutive threads -> consecutive banks).
    const int NV = 64 * (K / 4);
    for (int idx = threadIdx.x; idx < NV; idx += blockDim.x) {
        int row = idx & 63;
        int q   = idx >> 6;
        float4 v = make_float4(0.f, 0.f, 0.f, 0.f);
        if (n0 + row < N)
            v = reinterpret_cast<const float4*>(X)[(size_t)(n0 + row) * (K / 4) + q];
        if (LAYER == 2) {
            v.x = fmaxf(v.x, 0.f); v.y = fmaxf(v.y, 0.f);
            v.z = fmaxf(v.z, 0.f); v.w = fmaxf(v.w, 0.f);
        }
        xs[4 * q + 0][row] = v.x; xs[4 * q + 1][row] = v.y;
        xs[4 * q + 2][row] = v.z; xs[4 * q + 3][row] = v.w;
    }
    __syncthreads();

    int cg = threadIdx.x & 15;  // column group: cols [cg*4, cg*4+4)
    int i  = threadIdx.x >> 4;  // node group: nodes [i*8, i*8+8)

    for (int r = 0; r < 9; r++) {
        const float* W = (r < 8) ? (Wrel + (size_t)r * K * 64) : Wroot;
        unsigned long long acc[4][4];   // [col j][node-pair p]
#pragma unroll
        for (int j = 0; j < 4; j++)
#pragma unroll
            for (int p = 0; p < 4; p++) acc[j][p] = 0ull;

#pragma unroll 4
        for (int k = 0; k < K; k++) {
            float4 wv = *reinterpret_cast<const float4*>(W + (size_t)k * 64 + cg * 4);
            unsigned long long wb[4] = {bcast2(wv.x), bcast2(wv.y),
                                        bcast2(wv.z), bcast2(wv.w)};
            const ulonglong2* xp =
                reinterpret_cast<const ulonglong2*>(&xs[k][i * 8]);
            ulonglong2 xa = xp[0], xb = xp[1];
            unsigned long long xpair[4] = {xa.x, xa.y, xb.x, xb.y};
#pragma unroll
            for (int j = 0; j < 4; j++)
#pragma unroll
                for (int p = 0; p < 4; p++)
                    fma2(acc[j][p], xpair[p], wb[j]);
        }

#pragma unroll
        for (int n = 0; n < 8; n++) {
            int node = n0 + i * 8 + n;
            if (node < N) {
                int p = n >> 1;
                float c0 = (n & 1) ? hi2(acc[0][p]) : lo2(acc[0][p]);
                float c1 = (n & 1) ? hi2(acc[1][p]) : lo2(acc[1][p]);
                float c2 = (n & 1) ? hi2(acc[2][p]) : lo2(acc[2][p]);
                float c3 = (n & 1) ? hi2(acc[3][p]) : lo2(acc[3][p]);
                if (r < 8) {
                    *reinterpret_cast<float4*>(
                        g_xw + ((size_t)r * N + node) * 64 + cg * 4) =
                        make_float4(c0, c1, c2, c3);
                } else {
                    float4 b = reinterpret_cast<const float4*>(bias)[cg];
                    *reinterpret_cast<float4*>(
                        rootout + (size_t)node * 64 + cg * 4) =
                        make_float4(c0 + b.x, c1 + b.y, c2 + b.z, c3 + b.w);
                }
            }
        }
    }
}

// ---------------------------------------------------------------- Aggregation
// One WARP per dst node (no intra-warp divergence); lane handles 2 cols (float2).
// Unrolled x4: four independent 256B gathers in flight; two accumulator chains.
template <int LAYER>
__global__ void agg_kernel(float* __restrict__ Oarg, int N) {
    float* inout = (LAYER == 1) ? g_h : Oarg;

    int dst  = blockIdx.x * 8 + (threadIdx.x >> 5);
    int lane = threadIdx.x & 31;
    if (dst >= N) return;

    int start = g_rowstart[dst] + g_blocksum[dst >> 9];
    int dg    = g_deg[dst];

    float inv[RR];
#pragma unroll
    for (int r = 0; r < RR; r++) {
        int c = g_cnt[dst * RR + r];
        inv[r] = 1.0f / (float)(c > 0 ? c : 1);
    }

    const float* base = g_xw + (size_t)lane * 2;
    float2 accA = make_float2(0.f, 0.f);
    float2 accB = make_float2(0.f, 0.f);

    int i = 0;
    for (; i + 4 <= dg; i += 4) {
        int e0 = g_eidx[start + i];
        int e1 = g_eidx[start + i + 1];
        int e2 = g_eidx[start + i + 2];
        int e3 = g_eidx[start + i + 3];
        float2 v0 = *reinterpret_cast<const float2*>(
            base + ((size_t)(e0 & 7) * N + (e0 >> 3)) * 64);
        float2 v1 = *reinterpret_cast<const float2*>(
            base + ((size_t)(e1 & 7) * N + (e1 >> 3)) * 64);
        float2 v2 = *reinterpret_cast<const float2*>(
            base + ((size_t)(e2 & 7) * N + (e2 >> 3)) * 64);
        float2 v3 = *reinterpret_cast<const float2*>(
            base + ((size_t)(e3 & 7) * N + (e3 >> 3)) * 64);
        float s0 = inv[e0 & 7], s1 = inv[e1 & 7], s2 = inv[e2 & 7], s3 = inv[e3 & 7];
        accA.x = fmaf(v0.x, s0, accA.x); accA.y = fmaf(v0.y, s0, accA.y);
        accB.x = fmaf(v1.x, s1, accB.x); accB.y = fmaf(v1.y, s1, accB.y);
        accA.x = fmaf(v2.x, s2, accA.x); accA.y = fmaf(v2.y, s2, accA.y);
        accB.x = fmaf(v3.x, s3, accB.x); accB.y = fmaf(v3.y, s3, accB.y);
    }
    for (; i < dg; i++) {
        int e0 = g_eidx[start + i];
        float s0 = inv[e0 & 7];
        float2 v0 = *reinterpret_cast<const float2*>(
            base + ((size_t)(e0 & 7) * N + (e0 >> 3)) * 64);
        accA.x = fmaf(v0.x, s0, accA.x); accA.y = fmaf(v0.y, s0, accA.y);
    }

    float2* o = reinterpret_cast<float2*>(inout + (size_t)dst * 64 + lane * 2);
    float2 old = *o;
    old.x += accA.x + accB.x;
    old.y += accA.y + accB.y;
    *o = old;
}

// ---------------------------------------------------------------- launch
extern "C" void kernel_launch(void* const* d_in, const int* in_sizes, int n_in,
                              void* d_out, int out_size) {
    const float* x   = (const float*)d_in[0];
    const void*  ei  = d_in[1];
    const void*  et  = d_in[2];
    const float* W1r = (const float*)d_in[3];
    const float* W1o = (const float*)d_in[4];
    const float* b1  = (const float*)d_in[5];
    const float* W2r = (const float*)d_in[6];
    const float* W2o = (const float*)d_in[7];
    const float* b2  = (const float*)d_in[8];
    float* out = (float*)d_out;

    int N = in_sizes[0] / 128;
    int E = in_sizes[2];

    int nb = (N + 511) / 512;
    int gb = (N + 63) / 64;
    int ab = (N + 7) / 8;

    // gemm1 kept at launch index 3 (ncu capture window). Deps preserved on stream 0.
    dz_kernel<<<(N * RR + 255) / 256, 256>>>(ei, et, E, N, N * RR, N);      // 0
    count_kernel<<<(E + 255) / 256, 256>>>(ei, et, E, N);                    // 1
    scan1_kernel<<<nb, 512>>>(N);                                            // 2
    gemm_kernel<128, 1><<<gb, 128>>>(x, W1r, W1o, b1, nullptr, N);           // 3
    scan2_kernel<<<1, 512>>>(nb);                                            // 4
    fill_kernel<<<(E + 255) / 256, 256>>>(ei, et, E, N);                     // 5
    agg_kernel<1><<<ab, 256>>>(nullptr, N);                                  // 6
    gemm_kernel<64, 2><<<gb, 128>>>(nullptr, W2r, W2o, b2, out, N);          // 7
    agg_kernel<2><<<ab, 256>>>(out, N);                                      // 8
}